// round 4
// baseline (speedup 1.0000x reference)
#include <cuda_runtime.h>
#include <cuda_bf16.h>

// Problem constants
#define SIGMA   16
#define P       33
#define Hh      256
#define Wn      256
#define Bn      4
#define Kn      64
#define Nn      (Bn * Kn)          // 256 keypoints per side
#define NPATCH  (2 * Nn * Bn)      // 2048 total patches
#define C1      32
#define O1      31                 // conv1 out spatial
#define C2      64
#define O2      15                 // conv2 out spatial
#define OUTF    128
#define H1SZ    (C1 * O1 * O1)     // 30752

// smem layout (floats)
#define OFF_PATCH 0                       // 3*33*33 = 3267
#define OFF_W1    (OFF_PATCH + 3*P*P)     // 864
#define OFF_B1    (OFF_W1 + C1*27)        // 32
#define OFF_W2    (OFF_B1 + C1)           // 64*32*9 = 18432
#define OFF_B2    (OFF_W2 + C2*C1*9)      // 64
#define OFF_H1    (OFF_B2 + C2)           // 30752
#define OFF_GAP   (OFF_H1 + H1SZ)         // 64
#define SMEM_FLOATS (OFF_GAP + C2)        // 53475
#define SMEM_BYTES (SMEM_FLOATS * 4)      // 213900 B

typedef unsigned long long ull;

// Packed fp32x2 helpers (FFMA2 — only reachable via PTX fma.rn.f32x2)
#define PACK2(d, lo, hi)  asm("mov.b64 %0, {%1, %2};" : "=l"(d) : "f"(lo), "f"(hi))
#define UNPACK2(lo, hi, s) asm("mov.b64 {%0, %1}, %2;" : "=f"(lo), "=f"(hi) : "l"(s))
#define FMA2(d, a, b, c)  asm("fma.rn.f32x2 %0, %1, %2, %3;" : "=l"(d) : "l"(a), "l"(b), "l"(c))

__device__ float g_feat[(size_t)NPATCH * OUTF];
__device__ float g_part[256];

// ---------------------------------------------------------------------------
// Fused: crop + conv1 + conv2 + GAP + linear. One block per patch.
// ---------------------------------------------------------------------------
__global__ __launch_bounds__(512) void fused_kernel(
    const float* __restrict__ img_g, const float* __restrict__ img_s,
    const float* __restrict__ kp_g,  const float* __restrict__ kp_s,
    const float* __restrict__ w1,    const float* __restrict__ b1,
    const float* __restrict__ w2,    const float* __restrict__ b2,
    const float* __restrict__ wl,    const float* __restrict__ bl)
{
    extern __shared__ float sm[];
    float* patch = sm + OFF_PATCH;
    float* sw1   = sm + OFF_W1;
    float* sb1   = sm + OFF_B1;
    float* sw2   = sm + OFF_W2;
    float* sb2   = sm + OFF_B2;
    float* h1    = sm + OFF_H1;
    float* gap   = sm + OFF_GAP;

    const int tid  = threadIdx.x;
    const int p    = blockIdx.x;
    const int side = p >> 10;
    const int r    = p & 1023;
    const int n    = r >> 2;
    const int b    = r & 3;

    const float* kps = side ? kp_s : kp_g;
    const float* img = side ? img_s : img_g;

    const float kx = kps[n * 2 + 0] * 256.0f;
    const float ky = kps[n * 2 + 1] * 256.0f;
    int sx = (int)floorf(kx) - SIGMA;
    int sy = (int)floorf(ky) - SIGMA;
    sx = min(max(sx, 0), Wn - P);
    sy = min(max(sy, 0), Hh - P);

    // ---- stage patch + all weights ----
    for (int t = tid; t < 3 * P * P; t += 512) {
        int c   = t / (P * P);
        int rem = t - c * (P * P);
        int y   = rem / P;
        int x   = rem - y * P;
        patch[t] = img[(((size_t)b * 3 + c) * Hh + (sy + y)) * Wn + (sx + x)];
    }
    for (int t = tid; t < C1 * 27; t += 512) sw1[t] = w1[t];
    for (int t = tid; t < C2 * C1 * 9; t += 512) sw2[t] = w2[t];
    if (tid < C1) sb1[tid] = b1[tid];
    if (tid < C2) sb2[tid] = b2[tid];
    if (tid < C2) gap[tid] = 0.0f;
    __syncthreads();

    // ---- conv1: strips (oc-pair, oy); 496 threads; f32x2 over the oc pair ----
    if (tid < 16 * O1) {
        const int oy  = tid % O1;
        const int ocp = tid / O1;        // 0..15 -> oc = 2*ocp, 2*ocp+1
        ull acc[O1];
        {
            ull binit; PACK2(binit, sb1[2 * ocp], sb1[2 * ocp + 1]);
            #pragma unroll
            for (int x = 0; x < O1; x++) acc[x] = binit;
        }

        #pragma unroll
        for (int ic = 0; ic < 3; ic++) {
            #pragma unroll
            for (int kyy = 0; kyy < 3; kyy++) {
                const float* row = patch + (ic * P + oy + kyy) * P;
                const float* wp0 = sw1 + (2 * ocp)     * 27 + ic * 9 + kyy * 3;
                const float* wp1 = sw1 + (2 * ocp + 1) * 27 + ic * 9 + kyy * 3;
                ull wt0, wt1, wt2;
                PACK2(wt0, wp0[0], wp1[0]);
                PACK2(wt1, wp0[1], wp1[1]);
                PACK2(wt2, wp0[2], wp1[2]);
                #pragma unroll
                for (int x = 0; x < P; x++) {
                    float v = row[x];
                    ull vv; PACK2(vv, v, v);
                    if (x <= 30)           FMA2(acc[x],   vv, wt0, acc[x]);
                    if (x >= 1 && x <= 31) FMA2(acc[x-1], vv, wt1, acc[x-1]);
                    if (x >= 2)            FMA2(acc[x-2], vv, wt2, acc[x-2]);
                }
            }
        }
        float* o0 = h1 + ((2 * ocp)     * O1 + oy) * O1;
        float* o1 = h1 + ((2 * ocp + 1) * O1 + oy) * O1;
        #pragma unroll
        for (int x = 0; x < O1; x++) {
            float lo, hi; UNPACK2(lo, hi, acc[x]);
            o0[x] = fmaxf(lo, 0.0f);
            o1[x] = fmaxf(hi, 0.0f);
        }
    }
    __syncthreads();

    // ---- conv2 + relu + GAP: strips (oc-quad, oy); 240 threads; 2x f32x2 ----
    if (tid < 16 * O2) {
        const int oy  = tid % O2;
        const int ocq = tid / O2;        // 0..15 -> oc = 4*ocq..4*ocq+3
        ull accA[O2], accB[O2];          // A packs oc(0,1), B packs oc(2,3)
        {
            ull bA, bB;
            PACK2(bA, sb2[4 * ocq + 0], sb2[4 * ocq + 1]);
            PACK2(bB, sb2[4 * ocq + 2], sb2[4 * ocq + 3]);
            #pragma unroll
            for (int x = 0; x < O2; x++) { accA[x] = bA; accB[x] = bB; }
        }

        for (int ic = 0; ic < C1; ic++) {
            #pragma unroll
            for (int kyy = 0; kyy < 3; kyy++) {
                const float* row = h1 + (ic * O1 + 2 * oy + kyy) * O1;
                const float* wp0 = sw2 + ((4 * ocq + 0) * C1 + ic) * 9 + kyy * 3;
                const float* wp1 = sw2 + ((4 * ocq + 1) * C1 + ic) * 9 + kyy * 3;
                const float* wp2 = sw2 + ((4 * ocq + 2) * C1 + ic) * 9 + kyy * 3;
                const float* wp3 = sw2 + ((4 * ocq + 3) * C1 + ic) * 9 + kyy * 3;
                ull wA0, wA1, wA2, wB0, wB1, wB2;
                PACK2(wA0, wp0[0], wp1[0]); PACK2(wB0, wp2[0], wp3[0]);
                PACK2(wA1, wp0[1], wp1[1]); PACK2(wB1, wp2[1], wp3[1]);
                PACK2(wA2, wp0[2], wp1[2]); PACK2(wB2, wp2[2], wp3[2]);
                #pragma unroll
                for (int x = 0; x < O1; x++) {
                    float v = row[x];
                    ull vv; PACK2(vv, v, v);
                    if ((x & 1) == 0) {
                        if (x <= 28) {
                            const int o = x >> 1;
                            FMA2(accA[o], vv, wA0, accA[o]);
                            FMA2(accB[o], vv, wB0, accB[o]);
                        }
                        if (x >= 2) {
                            const int o = (x >> 1) - 1;
                            FMA2(accA[o], vv, wA2, accA[o]);
                            FMA2(accB[o], vv, wB2, accB[o]);
                        }
                    } else {
                        const int o = x >> 1;
                        FMA2(accA[o], vv, wA1, accA[o]);
                        FMA2(accB[o], vv, wB1, accB[o]);
                    }
                }
            }
        }
        // relu + per-thread GAP partials -> smem atomics
        float s0 = 0.0f, s1 = 0.0f, s2 = 0.0f, s3 = 0.0f;
        #pragma unroll
        for (int x = 0; x < O2; x++) {
            float lo, hi;
            UNPACK2(lo, hi, accA[x]);
            s0 += fmaxf(lo, 0.0f); s1 += fmaxf(hi, 0.0f);
            UNPACK2(lo, hi, accB[x]);
            s2 += fmaxf(lo, 0.0f); s3 += fmaxf(hi, 0.0f);
        }
        atomicAdd(&gap[4 * ocq + 0], s0);
        atomicAdd(&gap[4 * ocq + 1], s1);
        atomicAdd(&gap[4 * ocq + 2], s2);
        atomicAdd(&gap[4 * ocq + 3], s3);
    }
    __syncthreads();

    // ---- linear 64 -> 128 ----
    const float inv = 1.0f / (float)(O2 * O2);
    if (tid < OUTF) {
        float f = __ldg(&bl[tid]);
        const float* wrow = wl + tid * C2;
        #pragma unroll
        for (int c = 0; c < C2; c++) f = fmaf(gap[c] * inv, __ldg(&wrow[c]), f);
        g_feat[(size_t)p * OUTF + tid] = f;
    }
}

// ---------------------------------------------------------------------------
// loss = mean((fg - fs)^2), 2-stage deterministic reduction
// ---------------------------------------------------------------------------
__global__ __launch_bounds__(256) void loss_stage1(void)
{
    const int TOTAL = Nn * Bn * OUTF;     // 131072
    float s = 0.0f;
    for (int i = blockIdx.x * 256 + threadIdx.x; i < TOTAL; i += 256 * 256) {
        float d = g_feat[i] - g_feat[i + TOTAL];
        s = fmaf(d, d, s);
    }
    __shared__ float red[8];
    #pragma unroll
    for (int off = 16; off > 0; off >>= 1)
        s += __shfl_down_sync(0xFFFFFFFF, s, off);
    int wid = threadIdx.x >> 5;
    int lid = threadIdx.x & 31;
    if (lid == 0) red[wid] = s;
    __syncthreads();
    if (threadIdx.x == 0) {
        float t = 0.0f;
        #pragma unroll
        for (int w = 0; w < 8; w++) t += red[w];
        g_part[blockIdx.x] = t;
    }
}

__global__ __launch_bounds__(256) void loss_stage2(float* __restrict__ out)
{
    const int TOTAL = Nn * Bn * OUTF;
    float s = g_part[threadIdx.x];
    __shared__ float red[8];
    #pragma unroll
    for (int off = 16; off > 0; off >>= 1)
        s += __shfl_down_sync(0xFFFFFFFF, s, off);
    int wid = threadIdx.x >> 5;
    int lid = threadIdx.x & 31;
    if (lid == 0) red[wid] = s;
    __syncthreads();
    if (threadIdx.x == 0) {
        float t = 0.0f;
        #pragma unroll
        for (int w = 0; w < 8; w++) t += red[w];
        out[0] = t / (float)TOTAL;
    }
}

extern "C" void kernel_launch(void* const* d_in, const int* in_sizes, int n_in,
                              void* d_out, int out_size)
{
    const float* img_g = (const float*)d_in[0];
    const float* img_s = (const float*)d_in[1];
    const float* kp_g  = (const float*)d_in[2];
    const float* kp_s  = (const float*)d_in[3];
    const float* w1    = (const float*)d_in[4];
    const float* b1    = (const float*)d_in[5];
    const float* w2    = (const float*)d_in[6];
    const float* b2    = (const float*)d_in[7];
    const float* wl    = (const float*)d_in[8];
    const float* bl    = (const float*)d_in[9];
    float* out = (float*)d_out;

    static bool attr_set = false;
    if (!attr_set) {
        cudaFuncSetAttribute(fused_kernel,
                             cudaFuncAttributeMaxDynamicSharedMemorySize, SMEM_BYTES);
        attr_set = true;
    }

    fused_kernel<<<NPATCH, 512, SMEM_BYTES>>>(img_g, img_s, kp_g, kp_s,
                                              w1, b1, w2, b2, wl, bl);
    loss_stage1<<<256, 256>>>();
    loss_stage2<<<1, 256>>>(out);
}

// round 7
// speedup vs baseline: 1.8073x; 1.8073x over previous
#include <cuda_runtime.h>
#include <cuda_fp16.h>
#include <cuda_bf16.h>
#include <cstdint>

// Problem constants
#define SIGMA   16
#define P       33
#define Hh      256
#define Wn      256
#define Bn      4
#define Kn      64
#define Nn      (Bn * Kn)          // 256 keypoints per side
#define NPATCH  (2 * Nn * Bn)      // 2048 total patches
#define C1      32
#define O1      31                 // conv1 out spatial
#define C2      64
#define O2      15                 // conv2 out spatial (225 positions)
#define NPOS    (O2 * O2)          // 225
#define NPAD    232                // padded to 29 tiles of 8
#define NT      29
#define KTOT    288                // 32 ic * 3 * 3
#define KSTEPS  18                 // 288 / 16
#define OUTF    128
#define H1SZ    (C1 * O1 * O1)     // 30752
#define W2PAD   296                // padded halves per w2 row (bank-conflict-free A)

// smem element counts
#define N_PATCH  (3 * P * P)       // 3267 floats
#define N_SW1    (C1 * 27)         // 864 floats

__device__ float g_feat[(size_t)NPATCH * OUTF];
__device__ float g_part[256];

__device__ __forceinline__ uint32_t pack_h2(__half lo, __half hi) {
    uint32_t r;
    asm("mov.b32 %0, {%1, %2};" : "=r"(r)
        : "h"(__half_as_ushort(lo)), "h"(__half_as_ushort(hi)));
    return r;
}

__device__ __forceinline__ void mma16816(float& c0, float& c1, float& c2, float& c3,
                                         uint32_t a0, uint32_t a1, uint32_t a2, uint32_t a3,
                                         uint32_t b0, uint32_t b1) {
    asm volatile(
        "mma.sync.aligned.m16n8k16.row.col.f32.f16.f16.f32 "
        "{%0,%1,%2,%3}, {%4,%5,%6,%7}, {%8,%9}, {%0,%1,%2,%3};"
        : "+f"(c0), "+f"(c1), "+f"(c2), "+f"(c3)
        : "r"(a0), "r"(a1), "r"(a2), "r"(a3), "r"(b0), "r"(b1));
}

// ---------------------------------------------------------------------------
// Fused: crop + conv1 (fp32 scalar) + conv2 (HMMA fp16/fp32) + GAP + linear.
// One block per patch.
// ---------------------------------------------------------------------------
__global__ __launch_bounds__(512) void fused_kernel(
    const float* __restrict__ img_g, const float* __restrict__ img_s,
    const float* __restrict__ kp_g,  const float* __restrict__ kp_s,
    const float* __restrict__ w1,    const float* __restrict__ b1,
    const float* __restrict__ w2,    const float* __restrict__ b2,
    const float* __restrict__ wl,    const float* __restrict__ bl)
{
    extern __shared__ char smraw[];
    float*    patch  = (float*)smraw;              // 3267
    float*    sw1    = patch + N_PATCH;            // 864
    float*    sb1    = sw1 + N_SW1;                // 32
    float*    sb2    = sb1 + C1;                   // 64
    float*    gap    = sb2 + C2;                   // 64
    uint32_t* posoff = (uint32_t*)(gap + C2);      // 232
    uint32_t* tapoff = posoff + NPAD;              // 288
    __half*   h1h    = (__half*)(tapoff + KTOT);   // 30752 halves
    __half*   sw2h   = h1h + H1SZ;                 // 64*296 halves

    const int tid  = threadIdx.x;
    const int pidx = blockIdx.x;
    const int side = pidx >> 10;
    const int r    = pidx & 1023;
    const int n    = r >> 2;
    const int b    = r & 3;

    const float* kps = side ? kp_s : kp_g;
    const float* img = side ? img_s : img_g;

    const float kx = kps[n * 2 + 0] * 256.0f;
    const float ky = kps[n * 2 + 1] * 256.0f;
    int sx = (int)floorf(kx) - SIGMA;
    int sy = (int)floorf(ky) - SIGMA;
    sx = min(max(sx, 0), Wn - P);
    sy = min(max(sy, 0), Hh - P);

    // ---- stage: patch, weights, tables ----
    for (int t = tid; t < N_PATCH; t += 512) {
        int c   = t / (P * P);
        int rem = t - c * (P * P);
        int y   = rem / P;
        int x   = rem - y * P;
        patch[t] = img[(((size_t)b * 3 + c) * Hh + (sy + y)) * Wn + (sx + x)];
    }
    for (int t = tid; t < N_SW1; t += 512) sw1[t] = w1[t];
    for (int t = tid; t < C2 * KTOT; t += 512) {
        int oc = t / KTOT;
        int k  = t - oc * KTOT;
        sw2h[oc * W2PAD + k] = __float2half(w2[t]);
    }
    if (tid < C1) sb1[tid] = b1[tid];
    if (tid < C2) { sb2[tid] = b2[tid]; gap[tid] = 0.0f; }
    if (tid < NPAD) {
        int pp = min(tid, NPOS - 1);           // clamp padded positions (masked later)
        posoff[tid] = (uint32_t)((pp / O2) * (2 * O1) + (pp % O2) * 2);
    }
    if (tid < KTOT) {
        int ic  = tid / 9;
        int rem = tid - ic * 9;
        int kyy = rem / 3;
        int kxx = rem - kyy * 3;
        tapoff[tid] = (uint32_t)(ic * (O1 * O1) + kyy * O1 + kxx);
    }
    __syncthreads();

    // ---- conv1: strips (oc-pair, oy); 496 threads; fp32 scalar -> fp16 h1 ----
    if (tid < 16 * O1) {
        const int oy  = tid % O1;
        const int ocp = tid / O1;
        float acc0[O1], acc1[O1];
        const float bb0 = sb1[2 * ocp], bb1 = sb1[2 * ocp + 1];
        #pragma unroll
        for (int x = 0; x < O1; x++) { acc0[x] = bb0; acc1[x] = bb1; }

        #pragma unroll
        for (int ic = 0; ic < 3; ic++) {
            #pragma unroll
            for (int kyy = 0; kyy < 3; kyy++) {
                const float* row = patch + (ic * P + oy + kyy) * P;
                const float* wp0 = sw1 + (2 * ocp)     * 27 + ic * 9 + kyy * 3;
                const float* wp1 = sw1 + (2 * ocp + 1) * 27 + ic * 9 + kyy * 3;
                float a0 = wp0[0], a1 = wp0[1], a2 = wp0[2];
                float c0 = wp1[0], c1 = wp1[1], c2 = wp1[2];
                #pragma unroll
                for (int x = 0; x < P; x++) {
                    float v = row[x];
                    if (x <= 30) { acc0[x]   = fmaf(v, a0, acc0[x]);   acc1[x]   = fmaf(v, c0, acc1[x]); }
                    if (x >= 1 && x <= 31) { acc0[x-1] = fmaf(v, a1, acc0[x-1]); acc1[x-1] = fmaf(v, c1, acc1[x-1]); }
                    if (x >= 2) { acc0[x-2] = fmaf(v, a2, acc0[x-2]); acc1[x-2] = fmaf(v, c2, acc1[x-2]); }
                }
            }
        }
        __half* o0 = h1h + ((2 * ocp)     * O1 + oy) * O1;
        __half* o1 = h1h + ((2 * ocp + 1) * O1 + oy) * O1;
        #pragma unroll
        for (int x = 0; x < O1; x++) {
            o0[x] = __float2half(fmaxf(acc0[x], 0.0f));
            o1[x] = __float2half(fmaxf(acc1[x], 0.0f));
        }
    }
    __syncthreads();

    // ---- conv2 via HMMA: D[64 x 232] = W2[64 x 288] @ im2col(h1)[288 x 232] ----
    // 16 warps: mtile = wid&3 (16 oc rows each), nslice = wid>>2 (ntiles nslice,+4,...)
    {
        const int wid    = tid >> 5;
        const int lane   = tid & 31;
        const int g      = lane >> 2;   // group id 0..7
        const int t4     = lane & 3;    // thread in group
        const int mtile  = wid & 3;
        const int nslice = wid >> 2;
        const int mbase  = mtile * 16;

        const __half* aBase = sw2h + (mbase + g) * W2PAD + t4 * 2;
        const float bias0 = sb2[mbase + g];
        const float bias1 = sb2[mbase + 8 + g];

        float c[8][4];
        uint32_t poff[8];
        #pragma unroll
        for (int j = 0; j < 8; j++) {
            int nt = nslice + 4 * j;
            if (nt < NT) {
                poff[j] = posoff[nt * 8 + g];
                c[j][0] = bias0; c[j][1] = bias0;
                c[j][2] = bias1; c[j][3] = bias1;
            }
        }

        for (int ks = 0; ks < KSTEPS; ks++) {
            const __half* ap = aBase + ks * 16;
            uint32_t a0 = *(const uint32_t*)(ap);
            uint32_t a1 = *(const uint32_t*)(ap + 8 * W2PAD);
            uint32_t a2 = *(const uint32_t*)(ap + 8);
            uint32_t a3 = *(const uint32_t*)(ap + 8 * W2PAD + 8);
            const int kA = ks * 16 + t4 * 2;
            const uint32_t tA = tapoff[kA],     tB = tapoff[kA + 1];
            const uint32_t tC = tapoff[kA + 8], tD = tapoff[kA + 9];
            #pragma unroll
            for (int j = 0; j < 8; j++) {
                int nt = nslice + 4 * j;
                if (nt < NT) {
                    uint32_t po = poff[j];
                    uint32_t b0 = pack_h2(h1h[tA + po], h1h[tB + po]);
                    uint32_t b1 = pack_h2(h1h[tC + po], h1h[tD + po]);
                    mma16816(c[j][0], c[j][1], c[j][2], c[j][3],
                             a0, a1, a2, a3, b0, b1);
                }
            }
        }

        // epilogue: relu + masked GAP partials, reduce over t4, atomics into gap
        float vA = 0.0f, vB = 0.0f;
        #pragma unroll
        for (int j = 0; j < 8; j++) {
            int nt = nslice + 4 * j;
            if (nt < NT) {
                int pos0 = nt * 8 + t4 * 2;
                float m0 = (pos0     < NPOS) ? 1.0f : 0.0f;
                float m1 = (pos0 + 1 < NPOS) ? 1.0f : 0.0f;
                vA = fmaf(fmaxf(c[j][0], 0.0f), m0, vA);
                vA = fmaf(fmaxf(c[j][1], 0.0f), m1, vA);
                vB = fmaf(fmaxf(c[j][2], 0.0f), m0, vB);
                vB = fmaf(fmaxf(c[j][3], 0.0f), m1, vB);
            }
        }
        vA += __shfl_xor_sync(0xFFFFFFFF, vA, 1);
        vA += __shfl_xor_sync(0xFFFFFFFF, vA, 2);
        vB += __shfl_xor_sync(0xFFFFFFFF, vB, 1);
        vB += __shfl_xor_sync(0xFFFFFFFF, vB, 2);
        if (t4 == 0) {
            atomicAdd(&gap[mbase + g],     vA);
            atomicAdd(&gap[mbase + 8 + g], vB);
        }
    }
    __syncthreads();

    // ---- linear 64 -> 128 ----
    const float inv = 1.0f / (float)NPOS;
    if (tid < OUTF) {
        float f = __ldg(&bl[tid]);
        const float* wrow = wl + tid * C2;
        #pragma unroll
        for (int cc = 0; cc < C2; cc++) f = fmaf(gap[cc] * inv, __ldg(&wrow[cc]), f);
        g_feat[(size_t)pidx * OUTF + tid] = f;
    }
}

// smem size
#define SMEM_BYTES ((N_PATCH + N_SW1 + C1 + C2 + C2 + 0) * 4 \
                    + (NPAD + KTOT) * 4 \
                    + (H1SZ + C2 * W2PAD) * 2)

// ---------------------------------------------------------------------------
// loss = mean((fg - fs)^2), 2-stage deterministic reduction
// ---------------------------------------------------------------------------
__global__ __launch_bounds__(256) void loss_stage1(void)
{
    const int TOTAL = Nn * Bn * OUTF;     // 131072
    float s = 0.0f;
    for (int i = blockIdx.x * 256 + threadIdx.x; i < TOTAL; i += 256 * 256) {
        float d = g_feat[i] - g_feat[i + TOTAL];
        s = fmaf(d, d, s);
    }
    __shared__ float red[8];
    #pragma unroll
    for (int off = 16; off > 0; off >>= 1)
        s += __shfl_down_sync(0xFFFFFFFF, s, off);
    int wid = threadIdx.x >> 5;
    int lid = threadIdx.x & 31;
    if (lid == 0) red[wid] = s;
    __syncthreads();
    if (threadIdx.x == 0) {
        float t = 0.0f;
        #pragma unroll
        for (int w = 0; w < 8; w++) t += red[w];
        g_part[blockIdx.x] = t;
    }
}

__global__ __launch_bounds__(256) void loss_stage2(float* __restrict__ out)
{
    const int TOTAL = Nn * Bn * OUTF;
    float s = g_part[threadIdx.x];
    __shared__ float red[8];
    #pragma unroll
    for (int off = 16; off > 0; off >>= 1)
        s += __shfl_down_sync(0xFFFFFFFF, s, off);
    int wid = threadIdx.x >> 5;
    int lid = threadIdx.x & 31;
    if (lid == 0) red[wid] = s;
    __syncthreads();
    if (threadIdx.x == 0) {
        float t = 0.0f;
        #pragma unroll
        for (int w = 0; w < 8; w++) t += red[w];
        out[0] = t / (float)TOTAL;
    }
}

extern "C" void kernel_launch(void* const* d_in, const int* in_sizes, int n_in,
                              void* d_out, int out_size)
{
    const float* img_g = (const float*)d_in[0];
    const float* img_s = (const float*)d_in[1];
    const float* kp_g  = (const float*)d_in[2];
    const float* kp_s  = (const float*)d_in[3];
    const float* w1    = (const float*)d_in[4];
    const float* b1    = (const float*)d_in[5];
    const float* w2    = (const float*)d_in[6];
    const float* b2    = (const float*)d_in[7];
    const float* wl    = (const float*)d_in[8];
    const float* bl    = (const float*)d_in[9];
    float* out = (float*)d_out;

    static bool attr_set = false;
    if (!attr_set) {
        cudaFuncSetAttribute(fused_kernel,
                             cudaFuncAttributeMaxDynamicSharedMemorySize, SMEM_BYTES);
        attr_set = true;
    }

    fused_kernel<<<NPATCH, 512, SMEM_BYTES>>>(img_g, img_s, kp_g, kp_s,
                                              w1, b1, w2, b2, wl, bl);
    loss_stage1<<<256, 256>>>();
    loss_stage2<<<1, 256>>>(out);
}

// round 10
// speedup vs baseline: 3.2701x; 1.8093x over previous
#include <cuda_runtime.h>
#include <cuda_fp16.h>
#include <cuda_bf16.h>
#include <cstdint>

// Problem constants
#define SIGMA   16
#define P       33
#define Hh      256
#define Wn      256
#define Bn      4
#define Kn      64
#define Nn      (Bn * Kn)          // 256 keypoints per side
#define NPATCH  (2 * Nn * Bn)      // 2048 total patches
#define C1      32
#define O1      31                 // conv1 out spatial (961 positions)
#define C2      64
#define O2      15                 // conv2 out spatial (225 positions)
#define NPOS1   (O1 * O1)          // 961
#define NT1     121                // ceil(961/8)
#define NPOS2   (O2 * O2)          // 225
#define NT2     29                 // ceil(225/8)
#define OUTF    128

// conv1 GEMM: K padded 27 -> 48 (tap-major: k = tap*4 + ic, ic 0..3, ic3 = pad)
#define K1      48
#define W1PAD   56                 // halves per w1 row (conflict-free A)
// conv2 GEMM: K = 288 (k = tap*32 + ic), 18 k-steps
#define K2      288
#define W2PAD   296
#define S2      36                 // h1t halves per position (channel-last, padded)

// smem byte offsets
#define SM_H1T    0                       // 961*36*2 = 69192 -> 69200
#define SM_W2H    69200                   // 64*296*2 = 37888
#define SM_PATCH  107088                  // 1089*4*2 = 8712 -> 8720
#define SM_W1H    115808                  // 32*56*2 = 3584
#define SM_SB1    119392                  // 32*4
#define SM_SB2    119520                  // 64*4
#define SM_GAP    119776                  // 64*4
#define SM_P1OFF  120032                  // 968*4 = 3872
#define SM_P2OFF  123904                  // 232*4 = 928
#define SMEM_BYTES 124832

__device__ __half g_w1h[C1 * W1PAD];
__device__ __half g_w2h[C2 * W2PAD];
__device__ float  g_feat[(size_t)NPATCH * OUTF];
__device__ float  g_part[256];

__device__ __forceinline__ void mma16816(float& c0, float& c1, float& c2, float& c3,
                                         uint32_t a0, uint32_t a1, uint32_t a2, uint32_t a3,
                                         uint32_t b0, uint32_t b1) {
    asm volatile(
        "mma.sync.aligned.m16n8k16.row.col.f32.f16.f16.f32 "
        "{%0,%1,%2,%3}, {%4,%5,%6,%7}, {%8,%9}, {%0,%1,%2,%3};"
        : "+f"(c0), "+f"(c1), "+f"(c2), "+f"(c3)
        : "r"(a0), "r"(a1), "r"(a2), "r"(a3), "r"(b0), "r"(b1));
}

// ---------------------------------------------------------------------------
// Prep: permute + fp16-convert weights once (k-order = tap-major, ic-minor)
// ---------------------------------------------------------------------------
__global__ __launch_bounds__(512) void prep_kernel(
    const float* __restrict__ w1, const float* __restrict__ w2)
{
    int t = blockIdx.x * 512 + threadIdx.x;
    const int N1 = C1 * W1PAD;                 // 1792
    const int N2 = C2 * W2PAD;                 // 18944
    if (t < N1) {
        int oc = t / W1PAD, k = t - oc * W1PAD;
        float v = 0.0f;
        if (k < 36) {
            int tap = k >> 2, ic = k & 3;
            if (ic < 3) v = w1[oc * 27 + ic * 9 + tap];
        }
        g_w1h[t] = __float2half(v);
    } else if (t < N1 + N2) {
        int u = t - N1;
        int oc = u / W2PAD, k = u - oc * W2PAD;
        float v = 0.0f;
        if (k < K2) {
            int tap = k >> 5, ic = k & 31;
            v = w2[oc * K2 + ic * 9 + tap];
        }
        g_w2h[u] = __float2half(v);
    }
}

// ---------------------------------------------------------------------------
// Fused: crop + conv1(HMMA) + conv2(HMMA) + GAP + linear. One block / patch.
// ---------------------------------------------------------------------------
__global__ __launch_bounds__(512) void fused_kernel(
    const float* __restrict__ img_g, const float* __restrict__ img_s,
    const float* __restrict__ kp_g,  const float* __restrict__ kp_s,
    const float* __restrict__ b1,    const float* __restrict__ b2,
    const float* __restrict__ wl,    const float* __restrict__ bl)
{
    extern __shared__ char smraw[];
    __half*   h1t     = (__half*)(smraw + SM_H1T);    // [961][36] channel-last
    __half*   sw2h    = (__half*)(smraw + SM_W2H);
    __half*   patch_t = (__half*)(smraw + SM_PATCH);  // [1089][4] channel-last
    __half*   sw1h    = (__half*)(smraw + SM_W1H);
    float*    sb1     = (float*)(smraw + SM_SB1);
    float*    sb2     = (float*)(smraw + SM_SB2);
    float*    gap     = (float*)(smraw + SM_GAP);
    uint32_t* p1off   = (uint32_t*)(smraw + SM_P1OFF);
    uint32_t* p2off   = (uint32_t*)(smraw + SM_P2OFF);
    const char* h1b   = smraw + SM_H1T;
    const char* ptb   = smraw + SM_PATCH;

    const int tid  = threadIdx.x;
    const int pidx = blockIdx.x;
    const int side = pidx >> 10;
    const int r    = pidx & 1023;
    const int n    = r >> 2;
    const int b    = r & 3;

    const float* kps = side ? kp_s : kp_g;
    const float* img = side ? img_s : img_g;

    const float kx = kps[n * 2 + 0] * 256.0f;
    const float ky = kps[n * 2 + 1] * 256.0f;
    int sx = (int)floorf(kx) - SIGMA;
    int sy = (int)floorf(ky) - SIGMA;
    sx = min(max(sx, 0), Wn - P);
    sy = min(max(sy, 0), Hh - P);

    // ---- stage: patch (fp16 channel-last), weights (vector copy), tables ----
    for (int t = tid; t < P * P; t += 512) {
        int y = t / P, x = t - y * P;
        size_t base = (((size_t)b * 3) * Hh + (sy + y)) * Wn + (sx + x);
        float v0 = img[base];
        float v1 = img[base + (size_t)Hh * Wn];
        float v2 = img[base + 2 * (size_t)Hh * Wn];
        __half2* dst = (__half2*)(patch_t + t * 4);
        dst[0] = __floats2half2_rn(v0, v1);
        dst[1] = __floats2half2_rn(v2, 0.0f);
    }
    {
        const uint4* s2 = (const uint4*)g_w2h;
        uint4* d2 = (uint4*)sw2h;
        for (int t = tid; t < (C2 * W2PAD * 2) / 16; t += 512) d2[t] = s2[t];
        const uint4* s1 = (const uint4*)g_w1h;
        uint4* d1 = (uint4*)sw1h;
        for (int t = tid; t < (C1 * W1PAD * 2) / 16; t += 512) d1[t] = s1[t];
    }
    if (tid < C1) sb1[tid] = b1[tid];
    if (tid < C2) { sb2[tid] = b2[tid]; gap[tid] = 0.0f; }
    for (int t = tid; t < 968; t += 512) {               // FIX: grid-stride (968 > 512)
        int pp = min(t, NPOS1 - 1);
        p1off[t] = (uint32_t)((pp / O1) * P + (pp % O1));   // patch spatial (33-wide)
    }
    if (tid < 232) {
        int pp = min(tid, NPOS2 - 1);
        p2off[tid] = (uint32_t)((pp / O2) * (2 * O1) + (pp % O2) * 2);  // h1 spatial
    }
    __syncthreads();

    const int wid  = tid >> 5;
    const int lane = tid & 31;
    const int g    = lane >> 2;
    const int t4   = lane & 3;

    // ---- conv1 via HMMA: D[32 x 968] = W1[32 x 48] @ im2col(patch)[48 x 968] ----
    {
        const int mb      = (wid & 1) * 16;
        const int nslice  = wid >> 1;            // 0..7
        const int th      = t4 >> 1;
        const int icsel   = (t4 & 1) * 4;        // byte offset into 4-ch slot

        // preload A fragments for 3 k-steps
        uint32_t A[3][4];
        const __half* a1b = sw1h + (mb + g) * W1PAD + t4 * 2;
        #pragma unroll
        for (int ks = 0; ks < 3; ks++) {
            A[ks][0] = *(const uint32_t*)(a1b + ks * 16);
            A[ks][1] = *(const uint32_t*)(a1b + ks * 16 + 8 * W1PAD);
            A[ks][2] = *(const uint32_t*)(a1b + ks * 16 + 8);
            A[ks][3] = *(const uint32_t*)(a1b + ks * 16 + 8 * W1PAD + 8);
        }
        // tap spatial offsets (patch is 33-wide); taps >= 9 are A=0 padding -> clamp
        uint32_t tsA[3], tsB[3];
        #pragma unroll
        for (int ks = 0; ks < 3; ks++) {
            int ta = ks * 4 + th;
            int tb = ks * 4 + 2 + th;
            tsA[ks] = (ta < 9) ? (uint32_t)((ta / 3) * P + ta % 3) : 0u;
            tsB[ks] = (tb < 9) ? (uint32_t)((tb / 3) * P + tb % 3) : 0u;
        }
        const float bias0 = sb1[mb + g];
        const float bias1 = sb1[mb + 8 + g];

        for (int j = 0; j < 16; j++) {
            int nt = nslice + 8 * j;
            if (nt >= NT1) break;
            uint32_t pb = p1off[nt * 8 + g] * 8u + (uint32_t)icsel;  // byte base
            float c0 = bias0, c1 = bias0, c2 = bias1, c3 = bias1;
            #pragma unroll
            for (int ks = 0; ks < 3; ks++) {
                uint32_t b0 = *(const uint32_t*)(ptb + pb + tsA[ks] * 8u);
                uint32_t b1v = *(const uint32_t*)(ptb + pb + tsB[ks] * 8u);
                mma16816(c0, c1, c2, c3,
                         A[ks][0], A[ks][1], A[ks][2], A[ks][3], b0, b1v);
            }
            int p0 = nt * 8 + t4 * 2;
            if (p0 < NPOS1) {
                h1t[p0 * S2 + mb + g]     = __float2half(fmaxf(c0, 0.0f));
                h1t[p0 * S2 + mb + 8 + g] = __float2half(fmaxf(c2, 0.0f));
            }
            if (p0 + 1 < NPOS1) {
                h1t[(p0 + 1) * S2 + mb + g]     = __float2half(fmaxf(c1, 0.0f));
                h1t[(p0 + 1) * S2 + mb + 8 + g] = __float2half(fmaxf(c3, 0.0f));
            }
        }
    }
    __syncthreads();

    // ---- conv2 via HMMA: D[64 x 232] = W2[64 x 288] @ im2col(h1t)[288 x 232] ----
    {
        const int mtile  = wid & 3;
        const int nslice = wid >> 2;
        const int mbase  = mtile * 16;

        const __half* aBase = sw2h + (mbase + g) * W2PAD + t4 * 2;
        const float bias0 = sb2[mbase + g];
        const float bias1 = sb2[mbase + 8 + g];

        float c[8][4];
        uint32_t pbyte[8];
        #pragma unroll
        for (int j = 0; j < 8; j++) {
            int nt = nslice + 4 * j;
            if (nt < NT2) {
                pbyte[j] = p2off[nt * 8 + g] * (uint32_t)(S2 * 2) + (uint32_t)(t4 * 4);
                c[j][0] = bias0; c[j][1] = bias0;
                c[j][2] = bias1; c[j][3] = bias1;
            }
        }

        for (int ks = 0; ks < 18; ks++) {
            const __half* ap = aBase + ks * 16;
            uint32_t a0 = *(const uint32_t*)(ap);
            uint32_t a1 = *(const uint32_t*)(ap + 8 * W2PAD);
            uint32_t a2 = *(const uint32_t*)(ap + 8);
            uint32_t a3 = *(const uint32_t*)(ap + 8 * W2PAD + 8);
            const int tap  = ks >> 1;
            const uint32_t koff = (uint32_t)(((tap / 3) * O1 + tap % 3) * (S2 * 2)
                                             + (ks & 1) * 32);
            #pragma unroll
            for (int j = 0; j < 8; j++) {
                int nt = nslice + 4 * j;
                if (nt < NT2) {
                    uint32_t ba = pbyte[j] + koff;
                    uint32_t b0 = *(const uint32_t*)(h1b + ba);
                    uint32_t b1v = *(const uint32_t*)(h1b + ba + 16);
                    mma16816(c[j][0], c[j][1], c[j][2], c[j][3],
                             a0, a1, a2, a3, b0, b1v);
                }
            }
        }

        // epilogue: relu + masked GAP partials, reduce over t4 (cols), atomics
        float vA = 0.0f, vB = 0.0f;
        #pragma unroll
        for (int j = 0; j < 8; j++) {
            int nt = nslice + 4 * j;
            if (nt < NT2) {
                int pos0 = nt * 8 + t4 * 2;
                float m0 = (pos0     < NPOS2) ? 1.0f : 0.0f;
                float m1 = (pos0 + 1 < NPOS2) ? 1.0f : 0.0f;
                vA = fmaf(fmaxf(c[j][0], 0.0f), m0, vA);
                vA = fmaf(fmaxf(c[j][1], 0.0f), m1, vA);
                vB = fmaf(fmaxf(c[j][2], 0.0f), m0, vB);
                vB = fmaf(fmaxf(c[j][3], 0.0f), m1, vB);
            }
        }
        vA += __shfl_xor_sync(0xFFFFFFFF, vA, 1);
        vA += __shfl_xor_sync(0xFFFFFFFF, vA, 2);
        vB += __shfl_xor_sync(0xFFFFFFFF, vB, 1);
        vB += __shfl_xor_sync(0xFFFFFFFF, vB, 2);
        if (t4 == 0) {
            atomicAdd(&gap[mbase + g],     vA);
            atomicAdd(&gap[mbase + 8 + g], vB);
        }
    }
    __syncthreads();

    // ---- linear 64 -> 128 ----
    const float inv = 1.0f / (float)NPOS2;
    if (tid < OUTF) {
        float f = __ldg(&bl[tid]);
        const float* wrow = wl + tid * C2;
        #pragma unroll
        for (int cc = 0; cc < C2; cc++) f = fmaf(gap[cc] * inv, __ldg(&wrow[cc]), f);
        g_feat[(size_t)pidx * OUTF + tid] = f;
    }
}

// ---------------------------------------------------------------------------
// loss = mean((fg - fs)^2), 2-stage deterministic reduction
// ---------------------------------------------------------------------------
__global__ __launch_bounds__(256) void loss_stage1(void)
{
    const int TOTAL = Nn * Bn * OUTF;     // 131072
    float s = 0.0f;
    for (int i = blockIdx.x * 256 + threadIdx.x; i < TOTAL; i += 256 * 256) {
        float d = g_feat[i] - g_feat[i + TOTAL];
        s = fmaf(d, d, s);
    }
    __shared__ float red[8];
    #pragma unroll
    for (int off = 16; off > 0; off >>= 1)
        s += __shfl_down_sync(0xFFFFFFFF, s, off);
    int wid = threadIdx.x >> 5;
    int lid = threadIdx.x & 31;
    if (lid == 0) red[wid] = s;
    __syncthreads();
    if (threadIdx.x == 0) {
        float t = 0.0f;
        #pragma unroll
        for (int w = 0; w < 8; w++) t += red[w];
        g_part[blockIdx.x] = t;
    }
}

__global__ __launch_bounds__(256) void loss_stage2(float* __restrict__ out)
{
    const int TOTAL = Nn * Bn * OUTF;
    float s = g_part[threadIdx.x];
    __shared__ float red[8];
    #pragma unroll
    for (int off = 16; off > 0; off >>= 1)
        s += __shfl_down_sync(0xFFFFFFFF, s, off);
    int wid = threadIdx.x >> 5;
    int lid = threadIdx.x & 31;
    if (lid == 0) red[wid] = s;
    __syncthreads();
    if (threadIdx.x == 0) {
        float t = 0.0f;
        #pragma unroll
        for (int w = 0; w < 8; w++) t += red[w];
        out[0] = t / (float)TOTAL;
    }
}

extern "C" void kernel_launch(void* const* d_in, const int* in_sizes, int n_in,
                              void* d_out, int out_size)
{
    const float* img_g = (const float*)d_in[0];
    const float* img_s = (const float*)d_in[1];
    const float* kp_g  = (const float*)d_in[2];
    const float* kp_s  = (const float*)d_in[3];
    const float* w1    = (const float*)d_in[4];
    const float* b1    = (const float*)d_in[5];
    const float* w2    = (const float*)d_in[6];
    const float* b2    = (const float*)d_in[7];
    const float* wl    = (const float*)d_in[8];
    const float* bl    = (const float*)d_in[9];
    float* out = (float*)d_out;

    static bool attr_set = false;
    if (!attr_set) {
        cudaFuncSetAttribute(fused_kernel,
                             cudaFuncAttributeMaxDynamicSharedMemorySize, SMEM_BYTES);
        attr_set = true;
    }

    prep_kernel<<<41, 512>>>(w1, w2);
    fused_kernel<<<NPATCH, 512, SMEM_BYTES>>>(img_g, img_s, kp_g, kp_s,
                                              b1, b2, wl, bl);
    loss_stage1<<<256, 256>>>();
    loss_stage2<<<1, 256>>>(out);
}

// round 11
// speedup vs baseline: 3.9844x; 1.2184x over previous
#include <cuda_runtime.h>
#include <cuda_fp16.h>
#include <cuda_bf16.h>
#include <cstdint>

// Problem constants
#define SIGMA   16
#define P       33
#define Hh      256
#define Wn      256
#define Bn      4
#define Kn      64
#define Nn      (Bn * Kn)          // 256 keypoints per side
#define NPATCH  (2 * Nn * Bn)      // 2048 total patches
#define C1      32
#define O1      31                 // conv1 out spatial (961 positions)
#define C2      64
#define O2      15                 // conv2 out spatial (225 positions)
#define NPOS1   (O1 * O1)          // 961
#define NT1     121                // ceil(961/8)
#define NPOS2   (O2 * O2)          // 225
#define NT2     29                 // ceil(225/8)
#define OUTF    128

// conv1 GEMM: K padded 27 -> 48 (tap-major: k = tap*4 + ic, ic 0..3, ic3 = pad)
#define W1PAD   56                 // halves per w1 row (conflict-free A)
// conv2 GEMM: K = 288 (chunk = ks, within-chunk k permuted so B is contiguous)
#define K2      288
#define KS2     18
#define S2      40                 // h1t halves per position (stride 80B -> 8 mod 32 words)

// smem byte offsets
#define SM_H1T    0                        // 961*40*2 = 76880
#define SM_GAP    76880                    // 64*4
#define SM_SB2    77136                    // 64*4
#define SM_SB1    77392                    // 32*4
#define SM_P2OFF  77520                    // 232*4 = 928
#define SM_PATCH  78448                    // 1089*4*2 = 8712 -> 8720
#define SM_W1H    87168                    // 32*56*2 = 3584
#define SM_P1OFF  90752                    // 968*4 = 3872
#define SMEM_BYTES 94624

__device__ __half g_w1h[C1 * W1PAD];
__device__ uint4  g_w2a[4 * KS2 * 32];     // A fragments: [mtile][ks][lane] -> (a0,a1,a2,a3)
__device__ float  g_feat[(size_t)NPATCH * OUTF];
__device__ float  g_part[256];

__device__ __forceinline__ void mma16816(float& c0, float& c1, float& c2, float& c3,
                                         uint32_t a0, uint32_t a1, uint32_t a2, uint32_t a3,
                                         uint32_t b0, uint32_t b1) {
    asm volatile(
        "mma.sync.aligned.m16n8k16.row.col.f32.f16.f16.f32 "
        "{%0,%1,%2,%3}, {%4,%5,%6,%7}, {%8,%9}, {%0,%1,%2,%3};"
        : "+f"(c0), "+f"(c1), "+f"(c2), "+f"(c3)
        : "r"(a0), "r"(a1), "r"(a2), "r"(a3), "r"(b0), "r"(b1));
}

// within-chunk permutation: fragment row r -> logical ic offset (0..15)
__host__ __device__ __forceinline__ int permr(int r) {
    return (r & 1) | (((r >> 3) & 1) << 1) | (((r >> 1) & 3) << 2);
}

// ---------------------------------------------------------------------------
// Prep: w1 (tap-major, fp16, padded) + w2 A-fragments pre-swizzled per lane
// ---------------------------------------------------------------------------
__global__ __launch_bounds__(512) void prep_kernel(
    const float* __restrict__ w1, const float* __restrict__ w2)
{
    int t = blockIdx.x * 512 + threadIdx.x;
    const int N1 = C1 * W1PAD;                 // 1792
    const int N2 = 4 * KS2 * 32 * 4;           // 9216 u32 outputs
    if (t < N1) {
        int oc = t / W1PAD, k = t - oc * W1PAD;
        float v = 0.0f;
        if (k < 36) {
            int tap = k >> 2, ic = k & 3;
            if (ic < 3) v = w1[oc * 27 + ic * 9 + tap];
        }
        g_w1h[t] = __float2half(v);
    } else if (t < N1 + N2) {
        int u = t - N1;                        // ((mtile*18+ks)*32+lane)*4 + q
        int q    = u & 3;
        int lane = (u >> 2) & 31;
        int ks   = (u >> 7) % KS2;
        int mtile = u >> 7 / 1, mt = (u >> 7) / KS2;
        (void)mtile;
        int g  = lane >> 2;
        int t4 = lane & 3;
        int oc = mt * 16 + g + (q & 1) * 8;
        int kbase = 2 * t4 + (q >> 1) * 8;     // fragment rows kbase, kbase+1
        int tap    = ks >> 1;
        int icbase = (ks & 1) * 16;
        float vlo = w2[oc * K2 + (icbase + permr(kbase)) * 9 + tap];
        float vhi = w2[oc * K2 + (icbase + permr(kbase + 1)) * 9 + tap];
        __half2 h = __floats2half2_rn(vlo, vhi);
        ((uint32_t*)g_w2a)[u] = *(uint32_t*)&h;
    }
}

// ---------------------------------------------------------------------------
// Fused: crop + conv1(HMMA) + conv2(HMMA) + GAP + linear. One block / patch.
// ---------------------------------------------------------------------------
__global__ __launch_bounds__(512, 2) void fused_kernel(
    const float* __restrict__ img_g, const float* __restrict__ img_s,
    const float* __restrict__ kp_g,  const float* __restrict__ kp_s,
    const float* __restrict__ b1,    const float* __restrict__ b2,
    const float* __restrict__ wl,    const float* __restrict__ bl)
{
    extern __shared__ char smraw[];
    __half*   h1t     = (__half*)(smraw + SM_H1T);    // [961][40] channel-last
    float*    gap     = (float*)(smraw + SM_GAP);
    float*    sb2     = (float*)(smraw + SM_SB2);
    float*    sb1     = (float*)(smraw + SM_SB1);
    uint32_t* p2off   = (uint32_t*)(smraw + SM_P2OFF);
    __half*   patch_t = (__half*)(smraw + SM_PATCH);  // [1089][4] channel-last
    __half*   sw1h    = (__half*)(smraw + SM_W1H);
    uint32_t* p1off   = (uint32_t*)(smraw + SM_P1OFF);
    const char* h1b   = smraw + SM_H1T;
    const char* ptb   = smraw + SM_PATCH;

    const int tid  = threadIdx.x;
    const int pidx = blockIdx.x;
    const int side = pidx >> 10;
    const int r    = pidx & 1023;
    const int n    = r >> 2;
    const int b    = r & 3;

    const float* kps = side ? kp_s : kp_g;
    const float* img = side ? img_s : img_g;

    const float kx = kps[n * 2 + 0] * 256.0f;
    const float ky = kps[n * 2 + 1] * 256.0f;
    int sx = (int)floorf(kx) - SIGMA;
    int sy = (int)floorf(ky) - SIGMA;
    sx = min(max(sx, 0), Wn - P);
    sy = min(max(sy, 0), Hh - P);

    // ---- stage: patch (fp16 channel-last), w1, bias, tables ----
    for (int t = tid; t < P * P; t += 512) {
        int y = t / P, x = t - y * P;
        size_t base = (((size_t)b * 3) * Hh + (sy + y)) * Wn + (sx + x);
        float v0 = img[base];
        float v1 = img[base + (size_t)Hh * Wn];
        float v2 = img[base + 2 * (size_t)Hh * Wn];
        __half2* dst = (__half2*)(patch_t + t * 4);
        dst[0] = __floats2half2_rn(v0, v1);
        dst[1] = __floats2half2_rn(v2, 0.0f);
    }
    {
        const uint4* s1 = (const uint4*)g_w1h;
        uint4* d1 = (uint4*)sw1h;
        for (int t = tid; t < (C1 * W1PAD * 2) / 16; t += 512) d1[t] = s1[t];
    }
    if (tid < C1) sb1[tid] = b1[tid];
    if (tid < C2) { sb2[tid] = b2[tid]; gap[tid] = 0.0f; }
    for (int t = tid; t < 968; t += 512) {
        int pp = min(t, NPOS1 - 1);
        p1off[t] = (uint32_t)((pp / O1) * P + (pp % O1));   // patch spatial (33-wide)
    }
    if (tid < 232) {
        int pp = min(tid, NPOS2 - 1);
        p2off[tid] = (uint32_t)((pp / O2) * (2 * O1) + (pp % O2) * 2);  // h1 position idx
    }
    __syncthreads();

    const int wid  = tid >> 5;
    const int lane = tid & 31;
    const int g    = lane >> 2;
    const int t4   = lane & 3;

    // ---- conv1 via HMMA: D[32 x 968] = W1[32 x 48] @ im2col(patch)[48 x 968] ----
    {
        const int mb      = (wid & 1) * 16;
        const int nslice  = wid >> 1;            // 0..7
        const int th      = t4 >> 1;
        const int icsel   = (t4 & 1) * 4;        // byte offset into 4-ch slot

        uint32_t A[3][4];
        const __half* a1b = sw1h + (mb + g) * W1PAD + t4 * 2;
        #pragma unroll
        for (int ks = 0; ks < 3; ks++) {
            A[ks][0] = *(const uint32_t*)(a1b + ks * 16);
            A[ks][1] = *(const uint32_t*)(a1b + ks * 16 + 8 * W1PAD);
            A[ks][2] = *(const uint32_t*)(a1b + ks * 16 + 8);
            A[ks][3] = *(const uint32_t*)(a1b + ks * 16 + 8 * W1PAD + 8);
        }
        uint32_t tsA[3], tsB[3];
        #pragma unroll
        for (int ks = 0; ks < 3; ks++) {
            int ta = ks * 4 + th;
            int tb = ks * 4 + 2 + th;
            tsA[ks] = (ta < 9) ? (uint32_t)((ta / 3) * P + ta % 3) : 0u;
            tsB[ks] = (tb < 9) ? (uint32_t)((tb / 3) * P + tb % 3) : 0u;
        }
        const float bias0 = sb1[mb + g];
        const float bias1 = sb1[mb + 8 + g];

        for (int j = 0; j < 16; j++) {
            int nt = nslice + 8 * j;
            if (nt >= NT1) break;
            uint32_t pb = p1off[nt * 8 + g] * 8u + (uint32_t)icsel;
            float c0 = bias0, c1 = bias0, c2 = bias1, c3 = bias1;
            #pragma unroll
            for (int ks = 0; ks < 3; ks++) {
                uint32_t b0 = *(const uint32_t*)(ptb + pb + tsA[ks] * 8u);
                uint32_t b1v = *(const uint32_t*)(ptb + pb + tsB[ks] * 8u);
                mma16816(c0, c1, c2, c3,
                         A[ks][0], A[ks][1], A[ks][2], A[ks][3], b0, b1v);
            }
            int p0 = nt * 8 + t4 * 2;
            if (p0 < NPOS1) {
                h1t[p0 * S2 + mb + g]     = __float2half(fmaxf(c0, 0.0f));
                h1t[p0 * S2 + mb + 8 + g] = __float2half(fmaxf(c2, 0.0f));
            }
            if (p0 + 1 < NPOS1) {
                h1t[(p0 + 1) * S2 + mb + g]     = __float2half(fmaxf(c1, 0.0f));
                h1t[(p0 + 1) * S2 + mb + 8 + g] = __float2half(fmaxf(c3, 0.0f));
            }
        }
    }
    __syncthreads();

    // ---- conv2 via HMMA: D[64 x 232] = W2[64 x 288] @ im2col(h1t)[288 x 232] ----
    // A: pre-swizzled fragments from global (L2-hot), 1 LDG.128/ks, double-buffered.
    // B: single LDS.64 per mma (k-permuted, channel-contiguous).
    {
        const int mtile  = wid & 3;
        const int nslice = wid >> 2;
        const int mbase  = mtile * 16;

        const float bias0 = sb2[mbase + g];
        const float bias1 = sb2[mbase + 8 + g];

        float c[8][4];
        uint32_t pbyte[8];
        #pragma unroll
        for (int j = 0; j < 8; j++) {
            int nt = nslice + 4 * j;
            if (nt < NT2) {
                pbyte[j] = p2off[nt * 8 + g] * (uint32_t)(S2 * 2) + (uint32_t)(t4 * 8);
                c[j][0] = bias0; c[j][1] = bias0;
                c[j][2] = bias1; c[j][3] = bias1;
            }
        }

        const uint4* aPtr = g_w2a + (size_t)mtile * KS2 * 32 + lane;
        uint4 A = __ldg(aPtr);
        #pragma unroll 2
        for (int ks = 0; ks < KS2; ks++) {
            uint4 An;
            if (ks < KS2 - 1) An = __ldg(aPtr + (ks + 1) * 32);
            const int tap = ks >> 1;
            const uint32_t koff = (uint32_t)(((tap / 3) * O1 + tap % 3) * (S2 * 2)
                                             + (ks & 1) * 32);
            #pragma unroll
            for (int j = 0; j < 8; j++) {
                int nt = nslice + 4 * j;
                if (nt < NT2) {
                    const uint2 v = *(const uint2*)(h1b + pbyte[j] + koff);
                    mma16816(c[j][0], c[j][1], c[j][2], c[j][3],
                             A.x, A.y, A.z, A.w, v.x, v.y);
                }
            }
            A = An;
        }

        // epilogue: relu + masked GAP partials, reduce over t4 (cols), atomics
        float vA = 0.0f, vB = 0.0f;
        #pragma unroll
        for (int j = 0; j < 8; j++) {
            int nt = nslice + 4 * j;
            if (nt < NT2) {
                int pos0 = nt * 8 + t4 * 2;
                float m0 = (pos0     < NPOS2) ? 1.0f : 0.0f;
                float m1 = (pos0 + 1 < NPOS2) ? 1.0f : 0.0f;
                vA = fmaf(fmaxf(c[j][0], 0.0f), m0, vA);
                vA = fmaf(fmaxf(c[j][1], 0.0f), m1, vA);
                vB = fmaf(fmaxf(c[j][2], 0.0f), m0, vB);
                vB = fmaf(fmaxf(c[j][3], 0.0f), m1, vB);
            }
        }
        vA += __shfl_xor_sync(0xFFFFFFFF, vA, 1);
        vA += __shfl_xor_sync(0xFFFFFFFF, vA, 2);
        vB += __shfl_xor_sync(0xFFFFFFFF, vB, 1);
        vB += __shfl_xor_sync(0xFFFFFFFF, vB, 2);
        if (t4 == 0) {
            atomicAdd(&gap[mbase + g],     vA);
            atomicAdd(&gap[mbase + 8 + g], vB);
        }
    }
    __syncthreads();

    // ---- linear 64 -> 128 ----
    const float inv = 1.0f / (float)NPOS2;
    if (tid < OUTF) {
        float f = __ldg(&bl[tid]);
        const float* wrow = wl + tid * C2;
        #pragma unroll
        for (int cc = 0; cc < C2; cc++) f = fmaf(gap[cc] * inv, __ldg(&wrow[cc]), f);
        g_feat[(size_t)pidx * OUTF + tid] = f;
    }
}

// ---------------------------------------------------------------------------
// loss = mean((fg - fs)^2), 2-stage deterministic reduction
// ---------------------------------------------------------------------------
__global__ __launch_bounds__(256) void loss_stage1(void)
{
    const int TOTAL = Nn * Bn * OUTF;     // 131072
    float s = 0.0f;
    for (int i = blockIdx.x * 256 + threadIdx.x; i < TOTAL; i += 256 * 256) {
        float d = g_feat[i] - g_feat[i + TOTAL];
        s = fmaf(d, d, s);
    }
    __shared__ float red[8];
    #pragma unroll
    for (int off = 16; off > 0; off >>= 1)
        s += __shfl_down_sync(0xFFFFFFFF, s, off);
    int wid = threadIdx.x >> 5;
    int lid = threadIdx.x & 31;
    if (lid == 0) red[wid] = s;
    __syncthreads();
    if (threadIdx.x == 0) {
        float t = 0.0f;
        #pragma unroll
        for (int w = 0; w < 8; w++) t += red[w];
        g_part[blockIdx.x] = t;
    }
}

__global__ __launch_bounds__(256) void loss_stage2(float* __restrict__ out)
{
    const int TOTAL = Nn * Bn * OUTF;
    float s = g_part[threadIdx.x];
    __shared__ float red[8];
    #pragma unroll
    for (int off = 16; off > 0; off >>= 1)
        s += __shfl_down_sync(0xFFFFFFFF, s, off);
    int wid = threadIdx.x >> 5;
    int lid = threadIdx.x & 31;
    if (lid == 0) red[wid] = s;
    __syncthreads();
    if (threadIdx.x == 0) {
        float t = 0.0f;
        #pragma unroll
        for (int w = 0; w < 8; w++) t += red[w];
        out[0] = t / (float)TOTAL;
    }
}

extern "C" void kernel_launch(void* const* d_in, const int* in_sizes, int n_in,
                              void* d_out, int out_size)
{
    const float* img_g = (const float*)d_in[0];
    const float* img_s = (const float*)d_in[1];
    const float* kp_g  = (const float*)d_in[2];
    const float* kp_s  = (const float*)d_in[3];
    const float* w1    = (const float*)d_in[4];
    const float* b1    = (const float*)d_in[5];
    const float* w2    = (const float*)d_in[6];
    const float* b2    = (const float*)d_in[7];
    const float* wl    = (const float*)d_in[8];
    const float* bl    = (const float*)d_in[9];
    float* out = (float*)d_out;

    static bool attr_set = false;
    if (!attr_set) {
        cudaFuncSetAttribute(fused_kernel,
                             cudaFuncAttributeMaxDynamicSharedMemorySize, SMEM_BYTES);
        attr_set = true;
    }

    prep_kernel<<<22, 512>>>(w1, w2);
    fused_kernel<<<NPATCH, 512, SMEM_BYTES>>>(img_g, img_s, kp_g, kp_s,
                                              b1, b2, wl, bl);
    loss_stage1<<<256, 256>>>();
    loss_stage2<<<1, 256>>>(out);
}